// round 2
// baseline (speedup 1.0000x reference)
#include <cuda_runtime.h>
#include <cuda_bf16.h>

// Scratch (allocation-free: __device__ globals).
#define MAX_NODES 200000
__device__ float2 g_agg[MAX_NODES];   // .x = sum of x[src] into dst, .y = in-degree
__device__ float  g_s[MAX_NODES];     // s_i = dot(relu(h1_i), w2l)
__device__ float  g_b[MAX_NODES];     // b_i = sum_{j->i} s_j

// ---------------------------------------------------------------------------
// K0: zero scratch + output
// ---------------------------------------------------------------------------
__global__ void k_init(float* __restrict__ out, int n, int nb) {
    int i = blockIdx.x * blockDim.x + threadIdx.x;
    if (i < n) {
        g_agg[i] = make_float2(0.f, 0.f);
        g_b[i] = 0.f;
    }
    if (i < nb) out[i] = 0.f;
}

__device__ __forceinline__ void red_v2(float2* p, float v) {
    asm volatile("red.global.add.v2.f32 [%0], {%1, %2};"
                 :: "l"(p), "f"(v), "f"(1.0f) : "memory");
}

// ---------------------------------------------------------------------------
// K1: edge pass 1 — agg[dst] += {x[src], 1.0}   (4 edges per thread-iter)
// ---------------------------------------------------------------------------
__global__ void k_edge1(const int* __restrict__ src,
                        const int* __restrict__ dst,
                        const float* __restrict__ x, int E) {
    int tid = blockIdx.x * blockDim.x + threadIdx.x;
    int stride = gridDim.x * blockDim.x;
    int n4 = E >> 2;
    const int4* s4 = (const int4*)src;
    const int4* d4 = (const int4*)dst;
    for (int e = tid; e < n4; e += stride) {
        int4 S = __ldg(s4 + e);
        int4 D = __ldg(d4 + e);
        float x0 = __ldg(x + S.x);
        float x1 = __ldg(x + S.y);
        float x2 = __ldg(x + S.z);
        float x3 = __ldg(x + S.w);
        red_v2(&g_agg[D.x], x0);
        red_v2(&g_agg[D.y], x1);
        red_v2(&g_agg[D.z], x2);
        red_v2(&g_agg[D.w], x3);
    }
    // tail
    int base = n4 << 2;
    for (int e = base + tid; e < E; e += stride) {
        red_v2(&g_agg[__ldg(dst + e)], __ldg(x + __ldg(src + e)));
    }
}

// ---------------------------------------------------------------------------
// K2: per-node — compute s_i; fold (t_i + b2) into pooled output
// ---------------------------------------------------------------------------
__global__ void k_node(const float* __restrict__ x,
                       const int* __restrict__ batch,
                       const float* __restrict__ W1l, const float* __restrict__ b1,
                       const float* __restrict__ W1r,
                       const float* __restrict__ W2l, const float* __restrict__ b2,
                       const float* __restrict__ W2r,
                       float* __restrict__ out, int n) {
    int i = blockIdx.x * blockDim.x + threadIdx.x;
    if (i >= n) return;
    float2 ag = g_agg[i];
    float mean = ag.x / fmaxf(ag.y, 1.0f);
    float xv = x[i];
    float s = 0.f, t = 0.f;
#pragma unroll
    for (int k = 0; k < 16; k++) {
        float h = fmaf(xv, __ldg(W1r + k), fmaf(mean, __ldg(W1l + k), __ldg(b1 + k)));
        h = fmaxf(h, 0.f);
        s = fmaf(h, __ldg(W2l + k), s);
        t = fmaf(h, __ldg(W2r + k), t);
    }
    g_s[i] = s;
    int g = __ldg(batch + i);
    atomicAdd(out + g, t + __ldg(b2));
}

// ---------------------------------------------------------------------------
// K3: edge pass 2 — b[dst] += s[src]
// ---------------------------------------------------------------------------
__global__ void k_edge2(const int* __restrict__ src,
                        const int* __restrict__ dst, int E) {
    int tid = blockIdx.x * blockDim.x + threadIdx.x;
    int stride = gridDim.x * blockDim.x;
    int n4 = E >> 2;
    const int4* s4 = (const int4*)src;
    const int4* d4 = (const int4*)dst;
    for (int e = tid; e < n4; e += stride) {
        int4 S = __ldg(s4 + e);
        int4 D = __ldg(d4 + e);
        float v0 = __ldg(&g_s[S.x]);
        float v1 = __ldg(&g_s[S.y]);
        float v2 = __ldg(&g_s[S.z]);
        float v3 = __ldg(&g_s[S.w]);
        atomicAdd(&g_b[D.x], v0);
        atomicAdd(&g_b[D.y], v1);
        atomicAdd(&g_b[D.z], v2);
        atomicAdd(&g_b[D.w], v3);
    }
    int base = n4 << 2;
    for (int e = base + tid; e < E; e += stride) {
        atomicAdd(&g_b[__ldg(dst + e)], __ldg(&g_s[__ldg(src + e)]));
    }
}

// ---------------------------------------------------------------------------
// K4: final — out[batch[i]] += b_i / max(deg_i, 1)
// ---------------------------------------------------------------------------
__global__ void k_final(const int* __restrict__ batch,
                        float* __restrict__ out, int n) {
    int i = blockIdx.x * blockDim.x + threadIdx.x;
    if (i >= n) return;
    float bv = g_b[i];
    float deg = g_agg[i].y;
    atomicAdd(out + __ldg(batch + i), bv / fmaxf(deg, 1.0f));
}

// ---------------------------------------------------------------------------
extern "C" void kernel_launch(void* const* d_in, const int* in_sizes, int n_in,
                              void* d_out, int out_size) {
    const float* x     = (const float*)d_in[0];
    const int*   ei    = (const int*)d_in[1];
    const int*   batch = (const int*)d_in[2];

    // batch_size may or may not be materialized as an input tensor.
    // Layout without it: [x, ei, batch, W1l(16), b1(16), W1r(16), W2l(16), b2(1), W2r(16)]
    // Layout with it:    [x, ei, batch, bs(1), W1l(16), ...]
    int wb = 3;
    if (n_in >= 10 && in_sizes[3] == 1 && in_sizes[4] == 16) wb = 4;
    const float* W1l = (const float*)d_in[wb + 0];
    const float* b1  = (const float*)d_in[wb + 1];
    const float* W1r = (const float*)d_in[wb + 2];
    const float* W2l = (const float*)d_in[wb + 3];
    const float* b2  = (const float*)d_in[wb + 4];
    const float* W2r = (const float*)d_in[wb + 5];

    int N = in_sizes[0];           // 200000
    int E = in_sizes[1] / 2;       // 6400000
    int B = out_size;              // 512
    const int* src = ei;
    const int* dst = ei + E;
    float* out = (float*)d_out;

    int nodeBlocks = (N + 255) / 256;
    int edgeBlocks = 2048;

    k_init<<<nodeBlocks, 256>>>(out, N, B);
    k_edge1<<<edgeBlocks, 256>>>(src, dst, x, E);
    k_node<<<nodeBlocks, 256>>>(x, batch, W1l, b1, W1r, W2l, b2, W2r, out, N);
    k_edge2<<<edgeBlocks, 256>>>(src, dst, E);
    k_final<<<nodeBlocks, 256>>>(batch, out, N);
}